// round 4
// baseline (speedup 1.0000x reference)
#include <cuda_runtime.h>
#include <cuda_bf16.h>
#include <math.h>

#define SS   16      // samples per group
#define CC   128     // channels
#define GNN  256     // groups per batch item
#define NR   9       // max instance rows (bg + 8 fg labels)
#define MAXG 32768   // scratch capacity (G = 8192 here)

// per-group partial results (deterministic scratch, no atomics)
__device__ float g_gl[MAXG];
__device__ float g_gv[MAXG];

__global__ void __launch_bounds__(128) proposal_clloss_group_kernel(
    const int*   __restrict__ labs,    // [G*S]
    const float* __restrict__ feats,   // [bs, C, Gn, S]
    const int*   __restrict__ idxs,    // [G*S]
    const float* __restrict__ ctx)     // [C]
{
    __shared__ int   s_lab[SS];
    __shared__ int   s_idx[SS];
    __shared__ int   s_row[SS];          // instance row per sample, -1 = invalid
    __shared__ float s_inv[NR];          // 1/count per instance row
    __shared__ int   s_instnum;
    __shared__ int   s_hasbg;
    __shared__ float s_M[NR][CC];        // instance-mean rows
    __shared__ float s_sim[NR * NR];

    const int g   = blockIdx.x;
    const int tid = threadIdx.x;

    if (tid < SS) {
        s_lab[tid] = labs[g * SS + tid];
        s_idx[tid] = idxs[g * SS + tid];
    }
    __syncthreads();

    // ---------------- Phase A: per-group metadata (thread 0) ----------------
    if (tid == 0) {
        // u = number of distinct seed indices (count of first occurrences)
        int u = 0;
        #pragma unroll
        for (int i = 0; i < SS; i++) {
            bool first = true;
            for (int j = 0; j < i; j++) first &= (s_idx[j] != s_idx[i]);
            u += first ? 1 : 0;
        }
        // histogram of labels over first u samples; bin v = label+1 (0..8)
        int cnt[NR];
        #pragma unroll
        for (int v = 0; v < NR; v++) cnt[v] = 0;
        for (int i = 0; i < u; i++) cnt[s_lab[i] + 1]++;

        const int hasbg = (cnt[0] > 0) ? 1 : 0;
        // fg label -> instance row (1-based, ascending label order)
        int row_of[NR];
        row_of[0] = 0;                   // bg label -1 -> row 0
        int rr = 1;
        #pragma unroll
        for (int v = 1; v < NR; v++) {
            row_of[v] = rr;
            if (cnt[v] > 0) rr++;
        }
        const int fg_count = rr - 1;
        const int instnum  = fg_count + 1;
        s_instnum = instnum;
        s_hasbg   = hasbg;

        #pragma unroll
        for (int s = 0; s < SS; s++)
            s_row[s] = (s < u) ? row_of[s_lab[s] + 1] : -1;

        #pragma unroll
        for (int r = 0; r < NR; r++) s_inv[r] = 1.0f;
        if (hasbg) s_inv[0] = 1.0f / (float)cnt[0];
        #pragma unroll
        for (int v = 1; v < NR; v++)
            if (cnt[v] > 0) s_inv[row_of[v]] = 1.0f / (float)cnt[v];
    }
    __syncthreads();

    // ---------------- Phase B: per-channel instance sums --------------------
    // feat element (b,c,g_in,s) at ((b*C + c)*Gn + g_in)*S + s
    // with flat g: b*Gn = g - g_in  ->  base = (g - g_in)*C*S + g_in*S
    {
        const int    g_in  = g % GNN;
        const size_t base  = (size_t)(g - g_in) * (CC * SS) + (size_t)g_in * SS;
        const float4* fp   = reinterpret_cast<const float4*>(
                                feats + base + (size_t)tid * (GNN * SS));
        float4 q0 = fp[0], q1 = fp[1], q2 = fp[2], q3 = fp[3];
        float f[SS] = { q0.x, q0.y, q0.z, q0.w,  q1.x, q1.y, q1.z, q1.w,
                        q2.x, q2.y, q2.z, q2.w,  q3.x, q3.y, q3.z, q3.w };

        float acc[NR];
        #pragma unroll
        for (int r = 0; r < NR; r++) acc[r] = 0.0f;

        #pragma unroll
        for (int s = 0; s < SS; s++) {
            const int rs = s_row[s];     // uniform across the block
            #pragma unroll
            for (int r = 0; r < NR; r++)
                acc[r] += (rs == r) ? f[s] : 0.0f;
        }

        #pragma unroll
        for (int r = 0; r < NR; r++)
            s_M[r][tid] = acc[r] * s_inv[r];
        if (!s_hasbg)
            s_M[0][tid] = ctx[tid];      // row 0 = context compensation
    }
    __syncthreads();

    // ---------------- Phase C: sim = (M M^T) / T ----------------------------
    const int instnum = s_instnum;
    const int warp = tid >> 5;
    const int lane = tid & 31;
    {
        const int P = instnum * (instnum + 1) / 2;   // upper triangle incl diag
        for (int p = warp; p < P; p += 4) {
            int i = 0, rem = p;
            while (rem >= i + 1) { rem -= (i + 1); i++; }
            const int j = rem;
            float pa = 0.0f;
            #pragma unroll
            for (int k = 0; k < 4; k++)
                pa += s_M[i][lane + 32 * k] * s_M[j][lane + 32 * k];
            #pragma unroll
            for (int o = 16; o; o >>= 1)
                pa += __shfl_xor_sync(0xffffffffu, pa, o);
            if (lane == 0) {
                const float v = pa * 5.0f;           // 1/T, T=0.2
                s_sim[i * NR + j] = v;
                s_sim[j * NR + i] = v;
            }
        }
    }
    __syncthreads();

    // ---------------- Phase D: per-row logsumexp, group loss ----------------
    if (warp == 0) {
        float li = 0.0f;
        const int i = lane + 1;
        if (i < instnum) {
            float mx = -3.402823466e38f;
            for (int j = 0; j < instnum; j++)
                mx = fmaxf(mx, s_sim[i * NR + j]);
            float sum = 0.0f;
            for (int j = 0; j < instnum; j++)
                sum += expf(s_sim[i * NR + j] - mx);
            const float lse = mx + logf(sum);
            li = lse - s_sim[i * NR + i];
        }
        #pragma unroll
        for (int o = 16; o; o >>= 1)
            li += __shfl_xor_sync(0xffffffffu, li, o);
        if (lane == 0) {
            const float gv = (instnum >= 2) ? 1.0f : 0.0f;
            const float gl = (instnum >= 2) ? li / (float)(instnum - 1) : 0.0f;
            g_gl[g] = gl * gv;
            g_gv[g] = gv;
        }
    }
}

__global__ void __launch_bounds__(256) proposal_clloss_reduce_kernel(
    float* __restrict__ out, int G)
{
    __shared__ float snum[256];
    __shared__ float sden[256];
    float n = 0.0f, d = 0.0f;
    for (int i = threadIdx.x; i < G; i += 256) {
        n += g_gl[i];
        d += g_gv[i];
    }
    snum[threadIdx.x] = n;
    sden[threadIdx.x] = d;
    __syncthreads();
    for (int s = 128; s; s >>= 1) {
        if (threadIdx.x < s) {
            snum[threadIdx.x] += snum[threadIdx.x + s];
            sden[threadIdx.x] += sden[threadIdx.x + s];
        }
        __syncthreads();
    }
    if (threadIdx.x == 0)
        out[0] = snum[0] / sden[0] * 0.1f;
}

extern "C" void kernel_launch(void* const* d_in, const int* in_sizes, int n_in,
                              void* d_out, int out_size)
{
    const int*   labs  = (const int*)  d_in[0];  // proposal_instance_mask [bs,Gn,S]
    const float* feats = (const float*)d_in[1];  // grouped_features [bs,C,Gn,S]
    const int*   idxs  = (const int*)  d_in[2];  // grouped_indices [bs,Gn,S]
    const float* ctx   = (const float*)d_in[3];  // context_compen [1,C]
    float*       out   = (float*)d_out;

    const int G = in_sizes[0] / SS;              // total group count

    proposal_clloss_group_kernel<<<G, 128>>>(labs, feats, idxs, ctx);
    proposal_clloss_reduce_kernel<<<1, 256>>>(out, G);
}

// round 5
// speedup vs baseline: 1.7434x; 1.7434x over previous
#include <cuda_runtime.h>
#include <cuda_bf16.h>
#include <math.h>

#define SS     16      // samples per group
#define CC     128     // channels
#define GNN    256     // groups per batch item
#define NR     9       // max instance rows (bg + 8 fg labels)
#define MAXG   32768   // scratch capacity (G = 8192 here)
#define GP     2       // groups per CTA
#define CPAD   129     // padded channel pitch in staged smem
#define NTHR   256

// per-group partial results (deterministic scratch, no atomics)
__device__ float g_gl[MAXG];
__device__ float g_gv[MAXG];

// triangle pair LUT: p -> (i, j), j <= i, p = i(i+1)/2 + j, for instnum <= 9
__device__ __constant__ signed char TRI_I[45] = {
    0, 1,1, 2,2,2, 3,3,3,3, 4,4,4,4,4, 5,5,5,5,5,5,
    6,6,6,6,6,6,6, 7,7,7,7,7,7,7,7, 8,8,8,8,8,8,8,8,8 };
__device__ __constant__ signed char TRI_J[45] = {
    0, 0,1, 0,1,2, 0,1,2,3, 0,1,2,3,4, 0,1,2,3,4,5,
    0,1,2,3,4,5,6, 0,1,2,3,4,5,6,7, 0,1,2,3,4,5,6,7,8 };

__global__ void __launch_bounds__(NTHR) proposal_clloss_group_kernel(
    const int*   __restrict__ labs,    // [G*S]
    const float* __restrict__ feats,   // [bs, C, Gn, S]
    const int*   __restrict__ idxs,    // [G*S]
    const float* __restrict__ ctx)     // [C]
{
    __shared__ float sf[GP * SS * CPAD];   // staged features, [gs][s][c] transposed
    __shared__ float s_M[GP][NR][CC];      // instance-mean rows
    __shared__ float s_sim[GP][NR * NR];
    __shared__ int   s_row[GP][SS];
    __shared__ float s_inv[GP][NR];
    __shared__ int   s_instnum[GP];
    __shared__ int   s_hasbg[GP];

    const int tid   = threadIdx.x;
    const int warp  = tid >> 5;
    const int lane  = tid & 31;
    const int gbase = blockIdx.x * GP;

    // ----- issue coalesced feature loads early (regs) -------------------
    // 2 adjacent groups: per channel c, GP*SS floats = 128 B contiguous,
    // 128-B aligned (g_in even). flat = c*8 + gs*4 + q; 1024 float4 total.
    const int    g_in = gbase % GNN;
    const size_t base = (size_t)(gbase - g_in) * (CC * SS) + (size_t)g_in * SS;

    float4 v[4];
    int    dst_c[4], dst_gsq[4];
    #pragma unroll
    for (int it = 0; it < 4; it++) {
        const int flat = it * NTHR + tid;
        const int c  = flat >> 3;
        const int r  = flat & 7;        // gs*4 + q
        dst_c[it]   = c;
        dst_gsq[it] = r;
        const float* p = feats + base + (size_t)c * (GNN * SS) + (r >> 2) * SS + (r & 3) * 4;
        v[it] = *reinterpret_cast<const float4*>(p);
    }
    // ctx row (only used when no bg; load unconditionally to hide latency)
    float ctx_c0 = 0.0f, ctx_c1 = 0.0f;
    if (tid < CC) ctx_c0 = ctx[tid];            // for gs=0 thread mapping below
    ctx_c1 = ctx_c0;                            // same channel index pattern (see Phase B)

    // ----- Phase A: per-group metadata, warp w handles group w ----------
    if (warp < GP) {
        const int g  = gbase + warp;
        const int i  = lane;
        const bool smp = (i < SS);
        int idx_v = smp ? idxs[g * SS + i] : (0x40000000 + lane);
        int lab_v = smp ? labs[g * SS + i] : 0;

        unsigned m_idx = __match_any_sync(0xffffffffu, idx_v);
        const bool first = ((m_idx & ((1u << i) - 1u)) == 0u);
        const unsigned firstmask = __ballot_sync(0xffffffffu, first && smp);
        const int u = __popc(firstmask);

        const bool valid = smp && (i < u);
        const int  labm  = valid ? lab_v : (0x50000000 + lane);   // unique sentinel
        unsigned m_lab = __match_any_sync(0xffffffffu, labm);
        const int cnt  = __popc(m_lab);

        const unsigned mybit = valid ? (1u << (lab_v + 1)) : 0u;  // bit v = lab+1
        const unsigned P = __reduce_or_sync(0xffffffffu, mybit);

        const int hasbg    = (P & 1u) ? 1 : 0;
        const int fg_count = __popc(P >> 1);
        const int instnum  = fg_count + 1;

        int row = -1;
        if (valid) {
            if (lab_v < 0) row = 0;
            else           row = 1 + __popc((P >> 1) & ((1u << lab_v) - 1u));
        }
        if (smp) s_row[warp][i] = valid ? row : -1;
        if (lane < NR) s_inv[warp][lane] = 1.0f;
        __syncwarp();
        const bool leader = valid && ((m_lab & ((1u << i) - 1u)) == 0u);
        if (leader) s_inv[warp][row] = 1.0f / (float)cnt;
        if (lane == 0) { s_instnum[warp] = instnum; s_hasbg[warp] = hasbg; }
    }

    // ----- stage features to smem (transposed [gs][s][c]) ----------------
    #pragma unroll
    for (int it = 0; it < 4; it++) {
        const int c  = dst_c[it];
        const int gs = dst_gsq[it] >> 2;
        const int q  = dst_gsq[it] & 3;
        float* d = sf + (gs * SS + q * 4) * CPAD + c;
        d[0 * CPAD] = v[it].x;
        d[1 * CPAD] = v[it].y;
        d[2 * CPAD] = v[it].z;
        d[3 * CPAD] = v[it].w;
    }
    __syncthreads();

    // ----- Phase B: per-channel instance means ---------------------------
    {
        const int gs = tid >> 7;        // 0..1
        const int c  = tid & (CC - 1);  // 0..127

        float acc[NR];
        #pragma unroll
        for (int r = 0; r < NR; r++) acc[r] = 0.0f;

        #pragma unroll
        for (int s = 0; s < SS; s++) {
            const float f  = sf[(gs * SS + s) * CPAD + c];
            const int   rs = s_row[gs][s];            // uniform across half-block
            #pragma unroll
            for (int r = 0; r < NR; r++)
                acc[r] += (rs == r) ? f : 0.0f;
        }

        #pragma unroll
        for (int r = 0; r < NR; r++)
            s_M[gs][r][c] = acc[r] * s_inv[gs][r];
        if (!s_hasbg[gs])
            s_M[gs][0][c] = (gs == 0) ? ctx_c0 : ctx_c1;   // row 0 = context
    }
    __syncthreads();

    // ----- Phase C: sim = (M M^T) / T  (4 warps per group) ---------------
    {
        const int gs  = warp & 1;
        const int sub = warp >> 1;          // 0..3
        const int instnum = s_instnum[gs];
        const int P = instnum * (instnum + 1) / 2;
        for (int p = sub; p < P; p += 4) {
            const int i = TRI_I[p];
            const int j = TRI_J[p];
            float pa = 0.0f;
            #pragma unroll
            for (int k = 0; k < 4; k++)
                pa += s_M[gs][i][lane + 32 * k] * s_M[gs][j][lane + 32 * k];
            #pragma unroll
            for (int o = 16; o; o >>= 1)
                pa += __shfl_xor_sync(0xffffffffu, pa, o);
            if (lane == 0) {
                const float x = pa * 5.0f;         // 1/T, T = 0.2
                s_sim[gs][i * NR + j] = x;
                s_sim[gs][j * NR + i] = x;
            }
        }
    }
    __syncthreads();

    // ----- Phase D: per-row logsumexp, group loss ------------------------
    if (warp < GP) {
        const int gs = warp;
        const int instnum = s_instnum[gs];
        float li = 0.0f;
        const int i = lane + 1;
        if (i < instnum) {
            float mx = -3.402823466e38f;
            for (int j = 0; j < instnum; j++)
                mx = fmaxf(mx, s_sim[gs][i * NR + j]);
            float sum = 0.0f;
            for (int j = 0; j < instnum; j++)
                sum += __expf(s_sim[gs][i * NR + j] - mx);
            li = mx + __logf(sum) - s_sim[gs][i * NR + i];
        }
        #pragma unroll
        for (int o = 16; o; o >>= 1)
            li += __shfl_xor_sync(0xffffffffu, li, o);
        if (lane == 0) {
            const float gv = (instnum >= 2) ? 1.0f : 0.0f;
            const float gl = (instnum >= 2) ? li / (float)(instnum - 1) : 0.0f;
            g_gl[gbase + gs] = gl * gv;
            g_gv[gbase + gs] = gv;
        }
    }
}

__global__ void __launch_bounds__(1024) proposal_clloss_reduce_kernel(
    float* __restrict__ out, int G)
{
    __shared__ float sn[1024];
    __shared__ float sd[1024];
    const int tid = threadIdx.x;
    float n = 0.0f, d = 0.0f;
    int i = tid;
    for (; i + 3 * 1024 < G; i += 4 * 1024) {
        const float a0 = g_gl[i], a1 = g_gl[i + 1024], a2 = g_gl[i + 2048], a3 = g_gl[i + 3072];
        const float b0 = g_gv[i], b1 = g_gv[i + 1024], b2 = g_gv[i + 2048], b3 = g_gv[i + 3072];
        n += (a0 + a1) + (a2 + a3);
        d += (b0 + b1) + (b2 + b3);
    }
    for (; i < G; i += 1024) { n += g_gl[i]; d += g_gv[i]; }
    sn[tid] = n;
    sd[tid] = d;
    __syncthreads();
    for (int s = 512; s; s >>= 1) {
        if (tid < s) { sn[tid] += sn[tid + s]; sd[tid] += sd[tid + s]; }
        __syncthreads();
    }
    if (tid == 0) out[0] = sn[0] / sd[0] * 0.1f;
}

extern "C" void kernel_launch(void* const* d_in, const int* in_sizes, int n_in,
                              void* d_out, int out_size)
{
    const int*   labs  = (const int*)  d_in[0];  // proposal_instance_mask [bs,Gn,S]
    const float* feats = (const float*)d_in[1];  // grouped_features [bs,C,Gn,S]
    const int*   idxs  = (const int*)  d_in[2];  // grouped_indices [bs,Gn,S]
    const float* ctx   = (const float*)d_in[3];  // context_compen [1,C]
    float*       out   = (float*)d_out;

    const int G = in_sizes[0] / SS;              // total group count (8192)

    proposal_clloss_group_kernel<<<G / GP, NTHR>>>(labs, feats, idxs, ctx);
    proposal_clloss_reduce_kernel<<<1, 1024>>>(out, G);
}